// round 10
// baseline (speedup 1.0000x reference)
#include <cuda_runtime.h>

#define BATCH    131072
#define INP      5
#define HID      64
#define NEXP     40
#define OUTD     5
#define ROWS     64               // batch rows per block
#define NTHREADS 256
#define NBLK     (BATCH / ROWS)   // 2048

typedef unsigned int u32;

// ---------------------------------------------------------------------------
// JAX threefry2x32 with key = jax.random.key(1) -> (k1,k2) = (0,1)
// ---------------------------------------------------------------------------
__device__ __forceinline__ u32 rotl32(u32 x, int d) { return (x << d) | (x >> (32 - d)); }

__device__ __forceinline__ void threefry2x32_key01(u32 c0, u32 c1, u32& o0, u32& o1) {
    const u32 ks0 = 0u, ks1 = 1u, ks2 = 0x1BD11BDBu;  // 0x1BD11BDA ^ 0 ^ 1
    u32 x0 = c0 + ks0, x1 = c1 + ks1;
#define TFR(r) { x0 += x1; x1 = rotl32(x1, (r)); x1 ^= x0; }
    TFR(13) TFR(15) TFR(26) TFR(6)   x0 += ks1; x1 += ks2 + 1u;
    TFR(17) TFR(29) TFR(16) TFR(24)  x0 += ks2; x1 += ks0 + 2u;
    TFR(13) TFR(15) TFR(26) TFR(6)   x0 += ks0; x1 += ks1 + 3u;
    TFR(17) TFR(29) TFR(16) TFR(24)  x0 += ks1; x1 += ks2 + 4u;
    TFR(13) TFR(15) TFR(26) TFR(6)   x0 += ks2; x1 += ks0 + 5u;
#undef TFR
    o0 = x0; o1 = x1;
}

// Partitionable threefry random bits: ctr = (hi32(i)=0, lo32(i)), bits = x0 ^ x1,
// then JAX uniform(minval=tiny, maxval=1) bit-trick, then gumbel.
__device__ __forceinline__ float jax_gumbel32(u32 idx) {
    u32 a, b;
    threefry2x32_key01(0u, idx, a, b);
    u32 bits = a ^ b;
    float f = __uint_as_float(0x3f800000u | (bits >> 9)) - 1.0f;   // [0, 1)
    float u = fmaxf(f, 1.17549435e-38f);                            // minval = finfo.tiny
    return -logf(-logf(u));
}

// ---------------------------------------------------------------------------
// Fused kernel: encoder -> policy(softmax+categorical) -> 40-expert layer
// out[b] computed from Phase C REGISTER accumulators (no h readback).
// ---------------------------------------------------------------------------
__global__ __launch_bounds__(NTHREADS)
void trizrl_kernel(const float* __restrict__ x,
                   const float* __restrict__ enc_w, const float* __restrict__ enc_b,
                   const float* __restrict__ triz_w, const float* __restrict__ triz_b,
                   const float* __restrict__ pol_w, const float* __restrict__ pol_b,
                   const float* __restrict__ dec_w, const float* __restrict__ dec_b,
                   float* __restrict__ out) {
    __shared__ __align__(16) float zsm[ROWS * (HID + 1)];   // 16640 B
    __shared__ __align__(16) float wsm[HID * HID];          // 16384 B
    __shared__ __align__(16) float pool[2880];              // 11520 B: polw+xs (A/B) | decw (C)
    __shared__ float bsm[HID];                              // 256 B
    __shared__ int   acts[ROWS];                            // 256 B
    // total ~45 KB < 48 KB

    float* polw = pool;          // [0:2560)   pol_w staged, Phase A/B
    float* xs   = pool + 2560;   // [2560:2880) x rows staged, Phase A
    float* decw = pool;          // [0:320)    dec_w staged, Phase C (polw dead)

    // Output layout: concat(out[B,5], probs[B,40], actions[B], h[B,40,64]) fp32
    float* out_out   = out;
    float* out_probs = out + (size_t)BATCH * OUTD;
    float* out_act   = out_probs + (size_t)BATCH * NEXP;
    float* out_h     = out_act + (size_t)BATCH;

    const int tid  = threadIdx.x;
    const int blk  = blockIdx.x;
    const int brow = blk * ROWS;

    // ---- stage x rows (FULL 320 elements, strided); init out rows to dec_b ----
    for (int i = tid; i < ROWS * INP; i += NTHREADS) {
        xs[i] = x[(size_t)brow * INP + i];
        out_out[(size_t)brow * OUTD + i] = __ldg(&dec_b[i % OUTD]);
    }
    for (int i = tid; i < HID * NEXP; i += NTHREADS) polw[i] = pol_w[i];
    __syncthreads();

    // ---- Phase A: z = tanh(x @ enc_w + enc_b) -> zsm ----
    {
        const int j  = tid & (HID - 1);
        const int r0 = tid >> 6;          // 0..3
        float ew0 = __ldg(&enc_w[0 * HID + j]);
        float ew1 = __ldg(&enc_w[1 * HID + j]);
        float ew2 = __ldg(&enc_w[2 * HID + j]);
        float ew3 = __ldg(&enc_w[3 * HID + j]);
        float ew4 = __ldg(&enc_w[4 * HID + j]);
        float eb  = __ldg(&enc_b[j]);
#pragma unroll
        for (int it = 0; it < ROWS / 4; ++it) {
            int r = it * 4 + r0;
            const float* xr = &xs[r * INP];
            float a = eb;
            a = fmaf(xr[0], ew0, a);
            a = fmaf(xr[1], ew1, a);
            a = fmaf(xr[2], ew2, a);
            a = fmaf(xr[3], ew3, a);
            a = fmaf(xr[4], ew4, a);
            zsm[r * (HID + 1) + j] = tanhf(a);
        }
    }
    __syncthreads();

    // ---- Phase B: logits, gumbel-max categorical, softmax probs ----
    {
        const int r = tid >> 2;         // row within block, 4 lanes per row
        const int q = tid & 3;          // expert chunk: e in [q*10, q*10+10)
        const int b = brow + r;
        const float* zr = &zsm[r * (HID + 1)];

        float lg[10];
#pragma unroll
        for (int j = 0; j < 10; ++j) {
            int e = q * 10 + j;
            float acc = __ldg(&pol_b[e]);
#pragma unroll
            for (int k = 0; k < HID; ++k) acc = fmaf(zr[k], polw[k * NEXP + e], acc);
            lg[j] = acc;
        }

        const float NEG_INF = __int_as_float(0xff800000);
        float best = NEG_INF; int bestE = 0x7fffffff; float m = NEG_INF;
#pragma unroll
        for (int j = 0; j < 10; ++j) {
            int e = q * 10 + j;
            float g = jax_gumbel32((u32)(b * NEXP + e));
            float y = lg[j] + g;
            if (y > best) { best = y; bestE = e; }   // strict > keeps first index
            m = fmaxf(m, lg[j]);
        }
#pragma unroll
        for (int off = 1; off < 4; off <<= 1) {
            float ob = __shfl_xor_sync(0xffffffffu, best,  off, 4);
            int   oe = __shfl_xor_sync(0xffffffffu, bestE, off, 4);
            float om = __shfl_xor_sync(0xffffffffu, m,     off, 4);
            if (ob > best || (ob == best && oe < bestE)) { best = ob; bestE = oe; }
            m = fmaxf(m, om);
        }
        float s = 0.0f;
#pragma unroll
        for (int j = 0; j < 10; ++j) s += expf(lg[j] - m);
#pragma unroll
        for (int off = 1; off < 4; off <<= 1) s += __shfl_xor_sync(0xffffffffu, s, off, 4);
#pragma unroll
        for (int j = 0; j < 10; ++j) {
            int e = q * 10 + j;
            out_probs[(size_t)b * NEXP + e] = expf(lg[j] - m) / s;
        }
        if (q == 0) { out_act[b] = (float)bestE; acts[r] = bestE; }
    }
    __syncthreads();

    // ---- stage dec_w into smem (FULL 320 elements, strided; overlays dead polw) ----
    for (int i = tid; i < HID * OUTD; i += NTHREADS) decw[i] = dec_w[i];  // decw[f*5+j]
    // (the __syncthreads at the top of the e=0 iteration orders this before use)

    // ---- Phase C: h + fused register-direct decode of the selected expert ----
    const int ct = tid & 15;        // column tile: f0 = ct*4
    const int rt = tid >> 4;        // row tile:    r0 = rt*4
    const int f0 = ct * 4;
    const int r0 = rt * 4;

    for (int e = 0; e < NEXP; ++e) {
        __syncthreads();   // previous expert's wsm readers done / decw staged
        {
            const float4* wg = (const float4*)(triz_w + (size_t)e * HID * HID);
            float4* w4s = (float4*)wsm;
#pragma unroll
            for (int i = 0; i < 4; ++i) w4s[tid + i * NTHREADS] = wg[tid + i * NTHREADS];
            if (tid < HID) bsm[tid] = __ldg(&triz_b[e * HID + tid]);
        }
        __syncthreads();

        float acc[4][4];
#pragma unroll
        for (int i = 0; i < 4; ++i)
#pragma unroll
            for (int jj = 0; jj < 4; ++jj) acc[i][jj] = 0.0f;

        const float4* w4 = (const float4*)wsm;
#pragma unroll 8
        for (int k = 0; k < HID; ++k) {
            float4 w = w4[k * 16 + ct];
            float z0 = zsm[(r0 + 0) * (HID + 1) + k];
            float z1 = zsm[(r0 + 1) * (HID + 1) + k];
            float z2 = zsm[(r0 + 2) * (HID + 1) + k];
            float z3 = zsm[(r0 + 3) * (HID + 1) + k];
            acc[0][0] = fmaf(z0, w.x, acc[0][0]); acc[0][1] = fmaf(z0, w.y, acc[0][1]);
            acc[0][2] = fmaf(z0, w.z, acc[0][2]); acc[0][3] = fmaf(z0, w.w, acc[0][3]);
            acc[1][0] = fmaf(z1, w.x, acc[1][0]); acc[1][1] = fmaf(z1, w.y, acc[1][1]);
            acc[1][2] = fmaf(z1, w.z, acc[1][2]); acc[1][3] = fmaf(z1, w.w, acc[1][3]);
            acc[2][0] = fmaf(z2, w.x, acc[2][0]); acc[2][1] = fmaf(z2, w.y, acc[2][1]);
            acc[2][2] = fmaf(z2, w.z, acc[2][2]); acc[2][3] = fmaf(z2, w.w, acc[2][3]);
            acc[3][0] = fmaf(z3, w.x, acc[3][0]); acc[3][1] = fmaf(z3, w.y, acc[3][1]);
            acc[3][2] = fmaf(z3, w.z, acc[3][2]); acc[3][3] = fmaf(z3, w.w, acc[3][3]);
        }

        float b0 = bsm[f0 + 0], b1 = bsm[f0 + 1], b2 = bsm[f0 + 2], b3 = bsm[f0 + 3];
#pragma unroll
        for (int ri = 0; ri < 4; ++ri) {
            float4 o;
            o.x = fmaxf(acc[ri][0] + b0, 0.0f);
            o.y = fmaxf(acc[ri][1] + b1, 0.0f);
            o.z = fmaxf(acc[ri][2] + b2, 0.0f);
            o.w = fmaxf(acc[ri][3] + b3, 0.0f);
            int row = r0 + ri;
            size_t gb = (size_t)(brow + row);
            *(float4*)&out_h[((gb * NEXP + e) * HID) + f0] = o;

            // Register-direct decode: no h readback.
            if (acts[row] == e) {
#pragma unroll
                for (int j = 0; j < OUTD; ++j) {
                    float v;
                    v = o.x * decw[(f0 + 0) * OUTD + j];
                    v = fmaf(o.y, decw[(f0 + 1) * OUTD + j], v);
                    v = fmaf(o.z, decw[(f0 + 2) * OUTD + j], v);
                    v = fmaf(o.w, decw[(f0 + 3) * OUTD + j], v);
                    atomicAdd(&out_out[gb * OUTD + j], v);
                }
            }
        }
    }
}

// ---------------------------------------------------------------------------
extern "C" void kernel_launch(void* const* d_in, const int* in_sizes, int n_in,
                              void* d_out, int out_size) {
    const float* x      = (const float*)d_in[0];
    const float* enc_w  = (const float*)d_in[1];
    const float* enc_b  = (const float*)d_in[2];
    const float* triz_w = (const float*)d_in[3];
    const float* triz_b = (const float*)d_in[4];
    const float* pol_w  = (const float*)d_in[5];
    const float* pol_b  = (const float*)d_in[6];
    const float* dec_w  = (const float*)d_in[7];
    const float* dec_b  = (const float*)d_in[8];
    float* out = (float*)d_out;

    trizrl_kernel<<<NBLK, NTHREADS>>>(x, enc_w, enc_b, triz_w, triz_b,
                                      pol_w, pol_b, dec_w, dec_b, out);
}